// round 5
// baseline (speedup 1.0000x reference)
#include <cuda_runtime.h>
#include <cuda_bf16.h>
#include <math_constants.h>
#include <cstdint>

// Problem constants
#define BATCH  2
#define SEQ    2048
#define DMODEL 1024
#define NHEAD  16
#define HDIM   64
#define MTOT   (BATCH*SEQ)   // 4096

// ---------------- scratch (device globals; no allocation allowed) ----------
__device__ __align__(16) __nv_bfloat16 g_Qhi[BATCH*NHEAD*SEQ*HDIM];
__device__ __align__(16) __nv_bfloat16 g_Qlo[BATCH*NHEAD*SEQ*HDIM];
__device__ __align__(16) __nv_bfloat16 g_Khi[BATCH*NHEAD*SEQ*HDIM];
__device__ __align__(16) __nv_bfloat16 g_Klo[BATCH*NHEAD*SEQ*HDIM];
__device__ __align__(16) __nv_bfloat16 g_Vhi[BATCH*NHEAD*SEQ*HDIM];
__device__ __align__(16) __nv_bfloat16 g_Vlo[BATCH*NHEAD*SEQ*HDIM];
__device__ __align__(16) __nv_bfloat16 g_Ohi[MTOT*DMODEL];
__device__ __align__(16) __nv_bfloat16 g_Olo[MTOT*DMODEL];
__device__ __align__(16) __nv_bfloat16 g_Xhi[MTOT*DMODEL];
__device__ __align__(16) __nv_bfloat16 g_Xlo[MTOT*DMODEL];
__device__ __align__(16) __nv_bfloat16 g_Whi[DMODEL*DMODEL];
__device__ __align__(16) __nv_bfloat16 g_Wlo[DMODEL*DMODEL];

// ---------------- base-PTX helpers (compute_103-safe) ----------------------
__device__ __forceinline__ uint32_t smem_u32(const void* p) {
    uint32_t a;
    asm("{ .reg .u64 t; cvta.to.shared.u64 t, %1; cvt.u32.u64 %0, t; }"
        : "=r"(a) : "l"(p));
    return a;
}
__device__ __forceinline__ void cp_async16(uint32_t s, const void* g) {
    asm volatile("cp.async.cg.shared.global [%0], [%1], 16;"
                 :: "r"(s), "l"(g) : "memory");
}
#define CP_COMMIT() asm volatile("cp.async.commit_group;" ::: "memory")
#define CP_WAIT(N)  asm volatile("cp.async.wait_group %0;" :: "n"(N) : "memory")

__device__ __forceinline__ void ldsm4(uint32_t (&r)[4], uint32_t a) {
    asm volatile("ldmatrix.sync.aligned.m8n8.x4.shared.b16 {%0,%1,%2,%3}, [%4];"
                 : "=r"(r[0]), "=r"(r[1]), "=r"(r[2]), "=r"(r[3]) : "r"(a));
}
__device__ __forceinline__ void ldsm4t(uint32_t (&r)[4], uint32_t a) {
    asm volatile("ldmatrix.sync.aligned.m8n8.x4.trans.shared.b16 {%0,%1,%2,%3}, [%4];"
                 : "=r"(r[0]), "=r"(r[1]), "=r"(r[2]), "=r"(r[3]) : "r"(a));
}
__device__ __forceinline__ void mma16816(float (&d)[4], const uint32_t (&a)[4],
                                         uint32_t b0, uint32_t b1) {
    asm volatile(
        "mma.sync.aligned.m16n8k16.row.col.f32.bf16.bf16.f32 "
        "{%0,%1,%2,%3}, {%4,%5,%6,%7}, {%8,%9}, {%0,%1,%2,%3};"
        : "+f"(d[0]), "+f"(d[1]), "+f"(d[2]), "+f"(d[3])
        : "r"(a[0]), "r"(a[1]), "r"(a[2]), "r"(a[3]), "r"(b0), "r"(b1));
}
__device__ __forceinline__ uint32_t pack_hi(float x, float y, float& lx, float& ly) {
    __nv_bfloat16 hx = __float2bfloat16(x), hy = __float2bfloat16(y);
    lx = x - __bfloat162float(hx);
    ly = y - __bfloat162float(hy);
    __nv_bfloat162 p(hx, hy);
    return *(uint32_t*)&p;
}
__device__ __forceinline__ uint32_t pack2(float x, float y) {
    __nv_bfloat162 p(__float2bfloat16(x), __float2bfloat16(y));
    return *(uint32_t*)&p;
}

// ============================================================================
// Split fp32 -> bf16 hi/lo
// ============================================================================
__global__ __launch_bounds__(256)
void split_bf16(const float* __restrict__ x, __nv_bfloat16* __restrict__ hi,
                __nv_bfloat16* __restrict__ lo, int n4)
{
    int i = blockIdx.x * blockDim.x + threadIdx.x;
    if (i >= n4) return;
    float4 v = ((const float4*)x)[i];
    __nv_bfloat16 h0 = __float2bfloat16(v.x), h1 = __float2bfloat16(v.y);
    __nv_bfloat16 h2 = __float2bfloat16(v.z), h3 = __float2bfloat16(v.w);
    ((__nv_bfloat162*)hi)[i*2+0] = __nv_bfloat162(h0, h1);
    ((__nv_bfloat162*)hi)[i*2+1] = __nv_bfloat162(h2, h3);
    ((__nv_bfloat162*)lo)[i*2+0] = __nv_bfloat162(
        __float2bfloat16(v.x - __bfloat162float(h0)),
        __float2bfloat16(v.y - __bfloat162float(h1)));
    ((__nv_bfloat162*)lo)[i*2+1] = __nv_bfloat162(
        __float2bfloat16(v.z - __bfloat162float(h2)),
        __float2bfloat16(v.w - __bfloat162float(h3)));
}

// ============================================================================
// HMMA GEMM: Y[m,n] = sum_k X[m,k]*W[n,k] + bias[n], fp32 via bf16x3.
// OMODE 0: write f32 flat [M,N].  OMODE 1: write bf16 hi/lo in [B,H,S,DK].
// ============================================================================
#define ROWB   144
#define TILEB  (128*ROWB)
#define STAGEB (4*TILEB)
#define GEMM_SMEM (2*STAGEB)       // 147456

template<int OMODE>
__global__ __launch_bounds__(256, 1)
void gemm_tc(const __nv_bfloat16* __restrict__ Ahi, const __nv_bfloat16* __restrict__ Alo,
             const __nv_bfloat16* __restrict__ Bhi, const __nv_bfloat16* __restrict__ Blo,
             const float* __restrict__ bias, float* __restrict__ Yf,
             __nv_bfloat16* __restrict__ Yhi, __nv_bfloat16* __restrict__ Ylo)
{
    extern __shared__ char smem[];
    const uint32_t sb = smem_u32(smem);
    const int tid  = threadIdx.x;
    const int wid  = tid >> 5;
    const int lane = tid & 31;
    const int n0 = blockIdx.x * 128;
    const int m0 = blockIdx.y * 128;
    const int wm = (wid & 3) * 32;
    const int wn = (wid >> 2) * 64;

    auto issue_stage = [&](int ch, int buf) {
        const int k0 = ch * 64;
#pragma unroll
        for (int i = 0; i < 16; i++) {
            const int idx = tid + i * 256;
            const int mat = idx >> 10;
            const int r   = (idx >> 3) & 127;
            const int c   = idx & 7;
            const __nv_bfloat16* src =
                (mat < 2) ? (mat ? Alo : Ahi) : ((mat == 2) ? Bhi : Blo);
            const int rowbase = (mat < 2) ? m0 : n0;
            const void* g = src + (size_t)(rowbase + r) * DMODEL + k0 + c * 8;
            cp_async16(sb + buf * STAGEB + mat * TILEB + r * ROWB + c * 16, g);
        }
        CP_COMMIT();
    };

    float acc[2][8][4];
#pragma unroll
    for (int mt = 0; mt < 2; mt++)
#pragma unroll
        for (int nt = 0; nt < 8; nt++)
#pragma unroll
            for (int q = 0; q < 4; q++) acc[mt][nt][q] = 0.f;

    issue_stage(0, 0);

    for (int ch = 0; ch < 16; ch++) {
        const int buf = ch & 1;
        if (ch < 15) { issue_stage(ch + 1, buf ^ 1); CP_WAIT(1); }
        else CP_WAIT(0);
        __syncthreads();

        const uint32_t base = sb + buf * STAGEB;
        const int rlo = lane & 15;
        const int khalf = (lane >> 4) * 16;

#pragma unroll
        for (int ks = 0; ks < 4; ks++) {
            uint32_t ahi[2][4], alo[2][4];
#pragma unroll
            for (int mt = 0; mt < 2; mt++) {
                const uint32_t a = base + (wm + mt * 16 + rlo) * ROWB + ks * 32 + khalf;
                ldsm4(ahi[mt], a);
                ldsm4(alo[mt], a + TILEB);
            }
            uint32_t bhi[4][4], blo[4][4];
#pragma unroll
            for (int nb = 0; nb < 4; nb++) {
                const uint32_t a = base + 2 * TILEB +
                                   (wn + nb * 16 + rlo) * ROWB + ks * 32 + khalf;
                ldsm4(bhi[nb], a);
                ldsm4(blo[nb], a + TILEB);
            }
#pragma unroll
            for (int mt = 0; mt < 2; mt++)
#pragma unroll
                for (int nt = 0; nt < 8; nt++) {
                    const int nb = nt >> 1, sel = nt & 1;
                    mma16816(acc[mt][nt], ahi[mt], bhi[nb][sel], bhi[nb][2 + sel]);
                    mma16816(acc[mt][nt], ahi[mt], blo[nb][sel], blo[nb][2 + sel]);
                    mma16816(acc[mt][nt], alo[mt], bhi[nb][sel], bhi[nb][2 + sel]);
                }
        }
        __syncthreads();
    }

    const int grp = lane >> 2, t4 = lane & 3;
#pragma unroll
    for (int mt = 0; mt < 2; mt++) {
#pragma unroll
        for (int h2 = 0; h2 < 2; h2++) {
            const int m = m0 + wm + mt * 16 + grp + h2 * 8;
#pragma unroll
            for (int nt = 0; nt < 8; nt++) {
                const int n = n0 + wn + nt * 8 + t4 * 2;
                const float v0 = acc[mt][nt][h2 * 2 + 0] + bias[n];
                const float v1 = acc[mt][nt][h2 * 2 + 1] + bias[n + 1];
                if (OMODE == 0) {
                    float2 v; v.x = v0; v.y = v1;
                    *(float2*)&Yf[(size_t)m * DMODEL + n] = v;
                } else {
                    const int b  = m >> 11;
                    const int s  = m & (SEQ - 1);
                    const int h  = n >> 6;
                    const int dk = n & (HDIM - 1);
                    const size_t o = (((size_t)(b * NHEAD + h)) * SEQ + s) * HDIM + dk;
                    float l0, l1;
                    const uint32_t hp = pack_hi(v0, v1, l0, l1);
                    *(uint32_t*)&Yhi[o] = hp;
                    *(uint32_t*)&Ylo[o] = pack2(l0, l1);
                }
            }
        }
    }
}

// ============================================================================
// HMMA causal flash attention, bf16x3 precision.
// CTA: 128 q-rows of one (b,h), 256 threads (8 warps x 16 rows). K/V tiles 64.
// ============================================================================
#define F_QLO   (128*144)            // 18432 (Qhi size)
#define F_STG   (2*128*144)          // 36864
#define F_TILE  (64*144)             // 9216
#define F_STAGEB (4*F_TILE)          // 36864
#define FLASH_SMEM (F_STG + 2*F_STAGEB)  // 110592

__global__ __launch_bounds__(256, 1)
void flash_hmma(const __nv_bfloat16* __restrict__ Qhi_, const __nv_bfloat16* __restrict__ Qlo_,
                const __nv_bfloat16* __restrict__ Khi_, const __nv_bfloat16* __restrict__ Klo_,
                const __nv_bfloat16* __restrict__ Vhi_, const __nv_bfloat16* __restrict__ Vlo_,
                __nv_bfloat16* __restrict__ Ohi_, __nv_bfloat16* __restrict__ Olo_)
{
    extern __shared__ char smem[];
    const uint32_t sb = smem_u32(smem);
    const int tid = threadIdx.x, wid = tid >> 5, lane = tid & 31;
    const int qt = (int)(gridDim.x - 1) - (int)blockIdx.x;   // heavy tiles first
    const int bh = blockIdx.y;
    const int bb = bh >> 4, hd = bh & 15;
    const int wq = wid * 16;
    const int grp = lane >> 2, t4 = lane & 3;
    const int qbase = qt * 128;
    const size_t bhoff = (size_t)bh * SEQ * HDIM;

    // Q stage (group 0)
#pragma unroll
    for (int i = 0; i < 8; i++) {
        const int idx = tid + i * 256;           // 0..2047
        const int mat = idx >> 10;               // 0..1
        const int r = (idx >> 3) & 127, c = idx & 7;
        const __nv_bfloat16* src = (mat ? Qlo_ : Qhi_) + bhoff +
                                   (size_t)(qbase + r) * HDIM + c * 8;
        cp_async16(sb + mat * F_QLO + r * 144 + c * 16, src);
    }
    CP_COMMIT();

    const int njt = 2 * (qt + 1);
    auto issue_kv = [&](int jt, int buf) {
        const int k0 = jt * 64;
#pragma unroll
        for (int i = 0; i < 8; i++) {
            const int idx = tid + i * 256;       // 0..2047
            const int mat = idx >> 9;            // 0:Khi 1:Klo 2:Vhi 3:Vlo
            const int r = (idx >> 3) & 63, c = idx & 7;
            const __nv_bfloat16* src = (mat == 0) ? Khi_ : (mat == 1) ? Klo_
                                     : (mat == 2) ? Vhi_ : Vlo_;
            const void* g = src + bhoff + (size_t)(k0 + r) * HDIM + c * 8;
            cp_async16(sb + F_STG + buf * F_STAGEB + mat * F_TILE + r * 144 + c * 16, g);
        }
        CP_COMMIT();
    };
    issue_kv(0, 0);

    CP_WAIT(1);            // Q done (stage0 may be pending)
    __syncthreads();

    // Q fragments -> registers
    const int rlo = lane & 15;
    const int khalf = (lane >> 4) * 16;
    uint32_t qh[4][4], ql[4][4];
#pragma unroll
    for (int ks = 0; ks < 4; ks++) {
        const uint32_t a = sb + (wq + rlo) * 144 + ks * 32 + khalf;
        ldsm4(qh[ks], a);
        ldsm4(ql[ks], a + F_QLO);
    }

    float mr0 = -CUDART_INF_F, mr1 = -CUDART_INF_F, lr0 = 0.f, lr1 = 0.f;
    float out[8][4];
#pragma unroll
    for (int nf = 0; nf < 8; nf++)
#pragma unroll
        for (int q = 0; q < 4; q++) out[nf][q] = 0.f;

    const int r0g = qbase + wq + grp;       // global q row (first)
    const int r1g = r0g + 8;

    for (int jt = 0; jt < njt; jt++) {
        const int buf = jt & 1;
        if (jt + 1 < njt) { issue_kv(jt + 1, buf ^ 1); CP_WAIT(1); }
        else CP_WAIT(0);
        __syncthreads();
        const uint32_t kb = sb + F_STG + buf * F_STAGEB;

        // ---- S = Q K^T (bf16x3) ----
        float s[8][4];
#pragma unroll
        for (int nf = 0; nf < 8; nf++)
#pragma unroll
            for (int q = 0; q < 4; q++) s[nf][q] = 0.f;

#pragma unroll
        for (int ks = 0; ks < 4; ks++) {
            uint32_t kh[4][4], kl[4][4];
#pragma unroll
            for (int nb = 0; nb < 4; nb++) {
                const uint32_t a = kb + (nb * 16 + rlo) * 144 + ks * 32 + khalf;
                ldsm4(kh[nb], a);
                ldsm4(kl[nb], a + F_TILE);
            }
#pragma unroll
            for (int nf = 0; nf < 8; nf++) {
                const int nb = nf >> 1, sel = nf & 1;
                mma16816(s[nf], qh[ks], kh[nb][sel], kh[nb][2 + sel]);
                mma16816(s[nf], qh[ks], kl[nb][sel], kl[nb][2 + sel]);
                mma16816(s[nf], ql[ks], kh[nb][sel], kh[nb][2 + sel]);
            }
        }

        // ---- scale + causal mask ----
        const int k0 = jt * 64;
        const bool maskt = (jt >= njt - 2);
#pragma unroll
        for (int nf = 0; nf < 8; nf++) {
#pragma unroll
            for (int q = 0; q < 4; q++) s[nf][q] *= 0.125f;
            if (maskt) {
                const int c0 = k0 + nf * 8 + t4 * 2, c1 = c0 + 1;
                if (c0 > r0g) s[nf][0] = -1e9f;
                if (c1 > r0g) s[nf][1] = -1e9f;
                if (c0 > r1g) s[nf][2] = -1e9f;
                if (c1 > r1g) s[nf][3] = -1e9f;
            }
        }

        // ---- online softmax ----
        float mx0 = -CUDART_INF_F, mx1 = -CUDART_INF_F;
#pragma unroll
        for (int nf = 0; nf < 8; nf++) {
            mx0 = fmaxf(mx0, fmaxf(s[nf][0], s[nf][1]));
            mx1 = fmaxf(mx1, fmaxf(s[nf][2], s[nf][3]));
        }
        mx0 = fmaxf(mx0, __shfl_xor_sync(0xffffffffu, mx0, 1));
        mx0 = fmaxf(mx0, __shfl_xor_sync(0xffffffffu, mx0, 2));
        mx1 = fmaxf(mx1, __shfl_xor_sync(0xffffffffu, mx1, 1));
        mx1 = fmaxf(mx1, __shfl_xor_sync(0xffffffffu, mx1, 2));
        const float mn0 = fmaxf(mr0, mx0), mn1 = fmaxf(mr1, mx1);
        const float cr0 = __expf(mr0 - mn0), cr1 = __expf(mr1 - mn1);
        float sum0 = 0.f, sum1 = 0.f;
#pragma unroll
        for (int nf = 0; nf < 8; nf++) {
            s[nf][0] = __expf(s[nf][0] - mn0); sum0 += s[nf][0];
            s[nf][1] = __expf(s[nf][1] - mn0); sum0 += s[nf][1];
            s[nf][2] = __expf(s[nf][2] - mn1); sum1 += s[nf][2];
            s[nf][3] = __expf(s[nf][3] - mn1); sum1 += s[nf][3];
        }
        sum0 += __shfl_xor_sync(0xffffffffu, sum0, 1);
        sum0 += __shfl_xor_sync(0xffffffffu, sum0, 2);
        sum1 += __shfl_xor_sync(0xffffffffu, sum1, 1);
        sum1 += __shfl_xor_sync(0xffffffffu, sum1, 2);
        lr0 = lr0 * cr0 + sum0;
        lr1 = lr1 * cr1 + sum1;
        mr0 = mn0; mr1 = mn1;
#pragma unroll
        for (int nf = 0; nf < 8; nf++) {
            out[nf][0] *= cr0; out[nf][1] *= cr0;
            out[nf][2] *= cr1; out[nf][3] *= cr1;
        }

        // ---- O += P V (bf16x3) ----
        const int vrow = (lane & 7) + ((lane >> 4) << 3);
        const int vcol = (lane & 8);
#pragma unroll
        for (int ks = 0; ks < 4; ks++) {
            uint32_t ph[4], pl[4];
            {
                float l0, l1;
                ph[0] = pack_hi(s[2*ks][0],   s[2*ks][1],   l0, l1); pl[0] = pack2(l0, l1);
                ph[1] = pack_hi(s[2*ks][2],   s[2*ks][3],   l0, l1); pl[1] = pack2(l0, l1);
                ph[2] = pack_hi(s[2*ks+1][0], s[2*ks+1][1], l0, l1); pl[2] = pack2(l0, l1);
                ph[3] = pack_hi(s[2*ks+1][2], s[2*ks+1][3], l0, l1); pl[3] = pack2(l0, l1);
            }
#pragma unroll
            for (int nb = 0; nb < 4; nb++) {
                uint32_t vh[4], vl[4];
                const uint32_t a = kb + 2 * F_TILE + (ks * 16 + vrow) * 144 +
                                   (nb * 16 + vcol) * 2;
                ldsm4t(vh, a);
                ldsm4t(vl, a + F_TILE);
                mma16816(out[2*nb],   ph, vh[0], vh[2]);
                mma16816(out[2*nb],   ph, vl[0], vl[2]);
                mma16816(out[2*nb],   pl, vh[0], vh[2]);
                mma16816(out[2*nb+1], ph, vh[1], vh[3]);
                mma16816(out[2*nb+1], ph, vl[1], vl[3]);
                mma16816(out[2*nb+1], pl, vh[1], vh[3]);
            }
        }
        __syncthreads();   // protect buf before next issue overwrites it
    }

    // ---- epilogue: normalize, split hi/lo, write [B,S,D] ----
    const float inv0 = 1.f / lr0, inv1 = 1.f / lr1;
    const size_t bs0 = (size_t)(bb * SEQ + qbase + wq + grp) * DMODEL;
    const size_t bs1 = bs0 + 8 * DMODEL;
#pragma unroll
    for (int nf = 0; nf < 8; nf++) {
        const int col = hd * 64 + nf * 8 + t4 * 2;
        float l0, l1;
        uint32_t hp = pack_hi(out[nf][0] * inv0, out[nf][1] * inv0, l0, l1);
        *(uint32_t*)&Ohi_[bs0 + col] = hp;
        *(uint32_t*)&Olo_[bs0 + col] = pack2(l0, l1);
        hp = pack_hi(out[nf][2] * inv1, out[nf][3] * inv1, l0, l1);
        *(uint32_t*)&Ohi_[bs1 + col] = hp;
        *(uint32_t*)&Olo_[bs1 + col] = pack2(l0, l1);
    }
}

// ============================================================================
extern "C" void kernel_launch(void* const* d_in, const int* in_sizes, int n_in,
                              void* d_out, int out_size)
{
    (void)in_sizes; (void)n_in; (void)out_size;
    const float* q  = (const float*)d_in[0];
    const float* k  = (const float*)d_in[1];
    const float* v  = (const float*)d_in[2];
    const float* Wq = (const float*)d_in[4];
    const float* bq = (const float*)d_in[5];
    const float* Wk = (const float*)d_in[6];
    const float* bk = (const float*)d_in[7];
    const float* Wv = (const float*)d_in[8];
    const float* bv = (const float*)d_in[9];
    const float* Wo = (const float*)d_in[10];
    const float* bo = (const float*)d_in[11];
    float* out = (float*)d_out;

    __nv_bfloat16 *qhi, *qlo, *khi, *klo, *vhi, *vlo, *ohi, *olo, *xhi, *xlo, *whi, *wlo;
    cudaGetSymbolAddress((void**)&qhi, g_Qhi);
    cudaGetSymbolAddress((void**)&qlo, g_Qlo);
    cudaGetSymbolAddress((void**)&khi, g_Khi);
    cudaGetSymbolAddress((void**)&klo, g_Klo);
    cudaGetSymbolAddress((void**)&vhi, g_Vhi);
    cudaGetSymbolAddress((void**)&vlo, g_Vlo);
    cudaGetSymbolAddress((void**)&ohi, g_Ohi);
    cudaGetSymbolAddress((void**)&olo, g_Olo);
    cudaGetSymbolAddress((void**)&xhi, g_Xhi);
    cudaGetSymbolAddress((void**)&xlo, g_Xlo);
    cudaGetSymbolAddress((void**)&whi, g_Whi);
    cudaGetSymbolAddress((void**)&wlo, g_Wlo);

    cudaFuncSetAttribute(gemm_tc<0>, cudaFuncAttributeMaxDynamicSharedMemorySize, GEMM_SMEM);
    cudaFuncSetAttribute(gemm_tc<1>, cudaFuncAttributeMaxDynamicSharedMemorySize, GEMM_SMEM);
    cudaFuncSetAttribute(flash_hmma, cudaFuncAttributeMaxDynamicSharedMemorySize, FLASH_SMEM);

    const dim3 tb(256);
    const dim3 gridG(DMODEL/128, MTOT/128);     // (8, 32)
    const int nX4 = MTOT*DMODEL/4, nW4 = DMODEL*DMODEL/4;

    // Q projection
    split_bf16<<<nX4/256, tb>>>(q,  xhi, xlo, nX4);
    split_bf16<<<nW4/256, tb>>>(Wq, whi, wlo, nW4);
    gemm_tc<1><<<gridG, tb, GEMM_SMEM>>>(xhi, xlo, whi, wlo, bq, nullptr, qhi, qlo);
    // K projection
    split_bf16<<<nX4/256, tb>>>(k,  xhi, xlo, nX4);
    split_bf16<<<nW4/256, tb>>>(Wk, whi, wlo, nW4);
    gemm_tc<1><<<gridG, tb, GEMM_SMEM>>>(xhi, xlo, whi, wlo, bk, nullptr, khi, klo);
    // V projection
    split_bf16<<<nX4/256, tb>>>(v,  xhi, xlo, nX4);
    split_bf16<<<nW4/256, tb>>>(Wv, whi, wlo, nW4);
    gemm_tc<1><<<gridG, tb, GEMM_SMEM>>>(xhi, xlo, whi, wlo, bv, nullptr, vhi, vlo);

    // attention (HMMA)
    flash_hmma<<<dim3(SEQ/128, BATCH*NHEAD), tb, FLASH_SMEM>>>(
        qhi, qlo, khi, klo, vhi, vlo, ohi, olo);

    // output projection
    split_bf16<<<nW4/256, tb>>>(Wo, whi, wlo, nW4);
    gemm_tc<0><<<gridG, tb, GEMM_SMEM>>>(ohi, olo, whi, wlo, bo, out, nullptr, nullptr);
}